// round 1
// baseline (speedup 1.0000x reference)
#include <cuda_runtime.h>
#include <cuda_bf16.h>
#include <cstdint>

// ---------------- problem constants ----------------
#define NN 20000
#define EE 200000
#define DIM 256
#define HEADS 4
#define DH 64
#define INNER 256
#define EDIM 512
#define FF 1024
#define OUTD 128
#define DEPTH 2
#define LNEPS 1e-5f

// ---------------- scratch (device globals; no allocation allowed) ----------------
__device__ float g_x[NN * DIM];
__device__ float g_xn[NN * DIM];
__device__ float g_q[NN * INNER];
__device__ float g_kv[NN * 2 * INNER];
__device__ float g_e[(size_t)EE * INNER];      // 204.8 MB
__device__ float g_sim[EE * HEADS];
__device__ float g_m[NN * HEADS];
__device__ float g_den[NN * HEADS];
__device__ float g_agg[NN * INNER];
__device__ float g_y[NN * DIM];
__device__ float g_ff[NN * FF];

// ---------------- SGEMM: C[M,N] = A[M,K] @ B[K,N] + bias, optional GELU ----------------
// BM=BN=128, BK=16, 256 threads, 8x8 per-thread tile.
// Requires: N % 128 == 0, K % 16 == 0. M may be ragged (guarded).
template <int EPI>  // 0 = bias only, 1 = bias + tanh-GELU
__global__ __launch_bounds__(256) void sgemm_bias(
    const float* __restrict__ A, const float* __restrict__ B,
    const float* __restrict__ bias, float* __restrict__ C,
    int M, int N, int K)
{
    __shared__ float As[16][128];
    __shared__ float Bs[16][128];

    const int tid = threadIdx.x;
    const int bx = blockIdx.x, by = blockIdx.y;
    const int row0 = by * 128, col0 = bx * 128;
    const int tx = tid & 15, ty = tid >> 4;

    float acc[8][8];
#pragma unroll
    for (int i = 0; i < 8; i++)
#pragma unroll
        for (int j = 0; j < 8; j++) acc[i][j] = 0.f;

    for (int k0 = 0; k0 < K; k0 += 16) {
        // load A tile (128x16) as 512 float4s, transposed into As[k][m]
#pragma unroll
        for (int i = 0; i < 2; i++) {
            int f = tid + i * 256;
            int ar = f >> 2, ac = (f & 3) * 4;
            int grow = row0 + ar;
            float4 av = make_float4(0.f, 0.f, 0.f, 0.f);
            if (grow < M)
                av = *reinterpret_cast<const float4*>(A + (size_t)grow * K + k0 + ac);
            As[ac + 0][ar] = av.x;
            As[ac + 1][ar] = av.y;
            As[ac + 2][ar] = av.z;
            As[ac + 3][ar] = av.w;
        }
        // load B tile (16x128)
#pragma unroll
        for (int i = 0; i < 2; i++) {
            int f = tid + i * 256;
            int br = f >> 5, bc = (f & 31) * 4;
            float4 bv = *reinterpret_cast<const float4*>(B + (size_t)(k0 + br) * N + col0 + bc);
            *reinterpret_cast<float4*>(&Bs[br][bc]) = bv;
        }
        __syncthreads();

#pragma unroll
        for (int kk = 0; kk < 16; kk++) {
            float ra[8], rb[8];
#pragma unroll
            for (int i = 0; i < 8; i++) ra[i] = As[kk][ty * 8 + i];
#pragma unroll
            for (int j = 0; j < 8; j++) rb[j] = Bs[kk][tx * 8 + j];
#pragma unroll
            for (int i = 0; i < 8; i++)
#pragma unroll
                for (int j = 0; j < 8; j++) acc[i][j] += ra[i] * rb[j];
        }
        __syncthreads();
    }

#pragma unroll
    for (int i = 0; i < 8; i++) {
        int gr = row0 + ty * 8 + i;
        if (gr >= M) continue;
#pragma unroll
        for (int j = 0; j < 8; j++) {
            int gc = col0 + tx * 8 + j;
            float c = acc[i][j] + bias[gc];
            if (EPI == 1) {
                // tanh-approx GELU (matches jax.nn.gelu default approximate=True)
                float c3 = c * c * c;
                c = 0.5f * c * (1.f + tanhf(0.7978845608028654f * (c + 0.044715f * c3)));
            }
            C[(size_t)gr * N + gc] = c;
        }
    }
}

// ---------------- LayerNorm: warp per node, 256 dims (8 per lane) ----------------
__global__ void layernorm_k(const float* __restrict__ x, const float* __restrict__ g,
                            const float* __restrict__ b, float* __restrict__ out, int n)
{
    int w = (blockIdx.x * blockDim.x + threadIdx.x) >> 5;
    int lane = threadIdx.x & 31;
    if (w >= n) return;
    const float* xp = x + (size_t)w * DIM;
    float v[8], s = 0.f, sq = 0.f;
#pragma unroll
    for (int j = 0; j < 8; j++) {
        v[j] = xp[lane + j * 32];
        s += v[j];
        sq += v[j] * v[j];
    }
#pragma unroll
    for (int o = 16; o; o >>= 1) {
        s += __shfl_xor_sync(0xffffffffu, s, o);
        sq += __shfl_xor_sync(0xffffffffu, sq, o);
    }
    float mean = s * (1.f / DIM);
    float var = sq * (1.f / DIM) - mean * mean;
    float rstd = rsqrtf(var + LNEPS);
#pragma unroll
    for (int j = 0; j < 8; j++) {
        int d = lane + j * 32;
        out[(size_t)w * DIM + d] = (v[j] - mean) * rstd * g[d] + b[d];
    }
}

// ---------------- gated residual: x = y*g + res*(1-g), g = sigmoid([y,res,y-res]@W) ----------------
__global__ void gated_residual_k(const float* __restrict__ y, const float* __restrict__ res,
                                 const float* __restrict__ gw, float* __restrict__ xout, int n)
{
    int w = (blockIdx.x * blockDim.x + threadIdx.x) >> 5;
    int lane = threadIdx.x & 31;
    if (w >= n) return;
    const float* yp = y + (size_t)w * DIM;
    const float* rp = res + (size_t)w * DIM;
    float s = 0.f;
#pragma unroll
    for (int j = 0; j < 8; j++) {
        int d = lane + j * 32;
        float yv = yp[d], rv = rp[d];
        s += yv * gw[d] + rv * gw[DIM + d] + (yv - rv) * gw[2 * DIM + d];
    }
#pragma unroll
    for (int o = 16; o; o >>= 1) s += __shfl_xor_sync(0xffffffffu, s, o);
    float gate = 1.f / (1.f + expf(-s));
#pragma unroll
    for (int j = 0; j < 8; j++) {
        int d = lane + j * 32;
        float yv = yp[d], rv = rp[d];
        xout[(size_t)w * DIM + d] = yv * gate + rv * (1.f - gate);
    }
}

// ---------------- attention ----------------
__device__ __forceinline__ void atomicMaxFloat(float* addr, float val)
{
    int old = __float_as_int(*addr);
    while (__int_as_float(old) < val) {
        int prev = atomicCAS(reinterpret_cast<int*>(addr), old, __float_as_int(val));
        if (prev == old) break;
        old = prev;
    }
}

__global__ void fill_k(float* p, float v, int n)
{
    int i = blockIdx.x * blockDim.x + threadIdx.x;
    if (i < n) p[i] = v;
}

// warp per edge: sim[e,h] = scale * sum_d q[dst,h,d]*(k[src,h,d]+e[e,h,d]); running max into m
__global__ void sim_max_k(const float* __restrict__ q, const float* __restrict__ kv,
                          const float* __restrict__ eb, const int* __restrict__ src,
                          const int* __restrict__ dst, float* __restrict__ sim,
                          float* __restrict__ mbuf, int ne)
{
    int w = (blockIdx.x * blockDim.x + threadIdx.x) >> 5;
    int lane = threadIdx.x & 31;
    if (w >= ne) return;
    int s = src[w], d = dst[w];
    const float* qp = q + (size_t)d * INNER;
    const float* kp = kv + (size_t)s * (2 * INNER);  // k = first half of kv row
    const float* ep = eb + (size_t)w * INNER;
#pragma unroll
    for (int h = 0; h < HEADS; h++) {
        int base = h * DH + lane * 2;
        float2 qv = *reinterpret_cast<const float2*>(qp + base);
        float2 kvv = *reinterpret_cast<const float2*>(kp + base);
        float2 ev = *reinterpret_cast<const float2*>(ep + base);
        float p = qv.x * (kvv.x + ev.x) + qv.y * (kvv.y + ev.y);
#pragma unroll
        for (int o = 16; o; o >>= 1) p += __shfl_xor_sync(0xffffffffu, p, o);
        if (lane == 0) {
            float sv = p * 0.125f;  // DH^-0.5
            sim[w * HEADS + h] = sv;
            atomicMaxFloat(&mbuf[d * HEADS + h], sv);
        }
    }
}

// thread per (edge, head): p = exp(sim - m[dst]); den[dst] += p
__global__ void exp_den_k(float* __restrict__ sim, const float* __restrict__ mbuf,
                          const int* __restrict__ dst, float* __restrict__ den, int total)
{
    int i = blockIdx.x * blockDim.x + threadIdx.x;
    if (i >= total) return;
    int e = i >> 2, h = i & 3;
    int d = dst[e];
    float p = expf(sim[i] - mbuf[d * HEADS + h]);
    sim[i] = p;
    atomicAdd(&den[d * HEADS + h], p);
}

// warp per edge: agg[dst] += (p/den[dst]) * (v[src] + e)
__global__ void attn_agg_k(const float* __restrict__ kv, const float* __restrict__ eb,
                           const float* __restrict__ p, const float* __restrict__ den,
                           const int* __restrict__ src, const int* __restrict__ dst,
                           float* __restrict__ agg, int ne)
{
    int w = (blockIdx.x * blockDim.x + threadIdx.x) >> 5;
    int lane = threadIdx.x & 31;
    if (w >= ne) return;
    int s = src[w], d = dst[w];
    float attn[HEADS];
#pragma unroll
    for (int h = 0; h < HEADS; h++)
        attn[h] = p[w * HEADS + h] / den[d * HEADS + h];
    const float* vp = kv + (size_t)s * (2 * INNER) + INNER;  // v = second half
    const float* ep = eb + (size_t)w * INNER;
    float* ap = agg + (size_t)d * INNER;
#pragma unroll
    for (int j = 0; j < 8; j++) {
        int dim = lane + j * 32;
        int h = dim >> 6;
        atomicAdd(&ap[dim], attn[h] * (vp[dim] + ep[dim]));
    }
}

// ---------------- host side ----------------
static inline dim3 gemm_grid(int M, int N) { return dim3((N + 127) / 128, (M + 127) / 128); }

extern "C" void kernel_launch(void* const* d_in, const int* in_sizes, int n_in,
                              void* d_out, int out_size)
{
    const float* x_in      = (const float*)d_in[0];
    const float* edge_attr = (const float*)d_in[1];
    const int*   edge_idx  = (const int*)d_in[2];
    const float* ln1_g = (const float*)d_in[3];
    const float* ln1_b = (const float*)d_in[4];
    const float* Wq  = (const float*)d_in[5];
    const float* bq  = (const float*)d_in[6];
    const float* Wkv = (const float*)d_in[7];
    const float* bkv = (const float*)d_in[8];
    const float* We  = (const float*)d_in[9];
    const float* be  = (const float*)d_in[10];
    const float* Wo  = (const float*)d_in[11];
    const float* bo  = (const float*)d_in[12];
    const float* gate_attn_W = (const float*)d_in[13];
    const float* ln2_g = (const float*)d_in[14];
    const float* ln2_b = (const float*)d_in[15];
    const float* Wff1 = (const float*)d_in[16];
    const float* bff1 = (const float*)d_in[17];
    const float* Wff2 = (const float*)d_in[18];
    const float* bff2 = (const float*)d_in[19];
    const float* gate_ff_W = (const float*)d_in[20];
    const float* Wproj = (const float*)d_in[21];
    const float* bproj = (const float*)d_in[22];
    float* out = (float*)d_out;

    const int* src = edge_idx;       // row 0
    const int* dst = edge_idx + EE;  // row 1

    float *px, *pxn, *pq, *pkv, *pe, *psim, *pm, *pden, *pagg, *py, *pff;
    cudaGetSymbolAddress((void**)&px, g_x);
    cudaGetSymbolAddress((void**)&pxn, g_xn);
    cudaGetSymbolAddress((void**)&pq, g_q);
    cudaGetSymbolAddress((void**)&pkv, g_kv);
    cudaGetSymbolAddress((void**)&pe, g_e);
    cudaGetSymbolAddress((void**)&psim, g_sim);
    cudaGetSymbolAddress((void**)&pm, g_m);
    cudaGetSymbolAddress((void**)&pden, g_den);
    cudaGetSymbolAddress((void**)&pagg, g_agg);
    cudaGetSymbolAddress((void**)&py, g_y);
    cudaGetSymbolAddress((void**)&pff, g_ff);

    // x := input x
    cudaMemcpyAsync(px, x_in, (size_t)NN * DIM * sizeof(float), cudaMemcpyDeviceToDevice, 0);

    const int warpBlocks_N = (NN * 32 + 255) / 256;
    const int warpBlocks_E = (EE * 32 + 255) / 256;

    for (int d = 0; d < DEPTH; d++) {
        const float* l1g = ln1_g + d * DIM;
        const float* l1b = ln1_b + d * DIM;
        const float* wq  = Wq  + (size_t)d * DIM * INNER;
        const float* bqd = bq  + d * INNER;
        const float* wkv = Wkv + (size_t)d * DIM * 2 * INNER;
        const float* bkvd = bkv + d * 2 * INNER;
        const float* we  = We  + (size_t)d * EDIM * INNER;
        const float* bed = be  + d * INNER;
        const float* wo  = Wo  + (size_t)d * INNER * DIM;
        const float* bod = bo  + d * DIM;
        const float* gaw = gate_attn_W + (size_t)d * 3 * DIM;
        const float* l2g = ln2_g + d * DIM;
        const float* l2b = ln2_b + d * DIM;
        const float* wf1 = Wff1 + (size_t)d * DIM * FF;
        const float* bf1 = bff1 + d * FF;
        const float* wf2 = Wff2 + (size_t)d * FF * DIM;
        const float* bf2 = bff2 + d * DIM;
        const float* gfw = gate_ff_W + (size_t)d * 3 * DIM;

        // pre-norm
        layernorm_k<<<warpBlocks_N, 256>>>(px, l1g, l1b, pxn, NN);
        // q, kv projections
        sgemm_bias<0><<<gemm_grid(NN, INNER), 256>>>(pxn, wq, bqd, pq, NN, INNER, DIM);
        sgemm_bias<0><<<gemm_grid(NN, 2 * INNER), 256>>>(pxn, wkv, bkvd, pkv, NN, 2 * INNER, DIM);
        // edge projection (dominant GEMM)
        sgemm_bias<0><<<gemm_grid(EE, INNER), 256>>>(edge_attr, we, bed, pe, EE, INNER, EDIM);

        // attention: init reductions
        fill_k<<<(NN * HEADS + 255) / 256, 256>>>(pm, -3.0e38f, NN * HEADS);
        cudaMemsetAsync(pden, 0, (size_t)NN * HEADS * sizeof(float), 0);
        cudaMemsetAsync(pagg, 0, (size_t)NN * INNER * sizeof(float), 0);

        sim_max_k<<<warpBlocks_E, 256>>>(pq, pkv, pe, src, dst, psim, pm, EE);
        exp_den_k<<<(EE * HEADS + 255) / 256, 256>>>(psim, pm, dst, pden, EE * HEADS);
        attn_agg_k<<<warpBlocks_E, 256>>>(pkv, pe, psim, pden, src, dst, pagg, EE);

        // output projection + gated residual
        sgemm_bias<0><<<gemm_grid(NN, DIM), 256>>>(pagg, wo, bod, py, NN, DIM, INNER);
        gated_residual_k<<<warpBlocks_N, 256>>>(py, px, gaw, px, NN);

        // feedforward
        layernorm_k<<<warpBlocks_N, 256>>>(px, l2g, l2b, pxn, NN);
        sgemm_bias<1><<<gemm_grid(NN, FF), 256>>>(pxn, wf1, bf1, pff, NN, FF, DIM);
        sgemm_bias<0><<<gemm_grid(NN, DIM), 256>>>(pff, wf2, bf2, py, NN, DIM, FF);
        gated_residual_k<<<warpBlocks_N, 256>>>(py, px, gfw, px, NN);
    }

    // final projection
    sgemm_bias<0><<<gemm_grid(NN, OUTD), 256>>>(px, Wproj, bproj, out, NN, OUTD, DIM);
}

// round 2
// speedup vs baseline: 2.5837x; 2.5837x over previous
#include <cuda_runtime.h>
#include <cuda_bf16.h>
#include <cstdint>

// ---------------- problem constants ----------------
#define NN 20000
#define EE 200000
#define DIM 256
#define HEADS 4
#define DH 64
#define INNER 256
#define EDIM 512
#define FF 1024
#define OUTD 128
#define DEPTH 2
#define LNEPS 1e-5f

// ---------------- scratch (device globals; no allocation allowed) ----------------
__device__ float g_x[NN * DIM];
__device__ float g_xn[NN * DIM];
__device__ float g_q[NN * INNER];
__device__ float g_kv[NN * 2 * INNER];
__device__ float g_e[(size_t)EE * INNER];      // 204.8 MB
__device__ float g_sim[EE * HEADS];
__device__ float g_m[NN * HEADS];
__device__ float g_den[NN * HEADS];
__device__ float g_agg[NN * INNER];
__device__ float g_y[NN * DIM];
__device__ float g_ff[NN * FF];

// ---------------- TF32 tensor-core GEMM ----------------
// C[M,N] = A[M,K] @ B[K,N] + bias, optional tanh-GELU epilogue.
// BM=BN=128, BK=32, 256 threads (8 warps, 2x4), warp tile 64x32.
// mma.sync.aligned.m16n8k8.row.col.f32.tf32.tf32.f32
// Requires N % 128 == 0, K % 32 == 0; M ragged (guarded).

__device__ __forceinline__ uint32_t f2tf32(float f)
{
    uint32_t r;
    asm("cvt.rna.tf32.f32 %0, %1;" : "=r"(r) : "f"(f));
    return r;
}

__device__ __forceinline__ void mma_tf32(float* c, const uint32_t* a, const uint32_t* b)
{
    asm volatile(
        "mma.sync.aligned.m16n8k8.row.col.f32.tf32.tf32.f32 "
        "{%0,%1,%2,%3}, {%4,%5,%6,%7}, {%8,%9}, {%0,%1,%2,%3};"
        : "+f"(c[0]), "+f"(c[1]), "+f"(c[2]), "+f"(c[3])
        : "r"(a[0]), "r"(a[1]), "r"(a[2]), "r"(a[3]), "r"(b[0]), "r"(b[1]));
}

template <int EPI>  // 0 = bias only, 1 = bias + tanh-GELU
__global__ __launch_bounds__(256, 2) void tgemm_bias(
    const float* __restrict__ A, const float* __restrict__ B,
    const float* __restrict__ bias, float* __restrict__ C,
    int M, int N, int K)
{
    __shared__ uint32_t As[128][36];   // [m][k], pad 4 -> conflict-free frag loads
    __shared__ uint32_t Bs[32][132];   // [k][n], pad 4

    const int tid = threadIdx.x;
    const int warp = tid >> 5, lane = tid & 31;
    const int warpM = warp >> 2;       // 0..1 -> 64-row slab
    const int warpN = warp & 3;        // 0..3 -> 32-col slab
    const int g = lane >> 2, tg = lane & 3;

    const int row0 = blockIdx.y * 128, col0 = blockIdx.x * 128;

    float acc[4][4][4];
#pragma unroll
    for (int i = 0; i < 4; i++)
#pragma unroll
        for (int j = 0; j < 4; j++)
#pragma unroll
            for (int r = 0; r < 4; r++) acc[i][j][r] = 0.f;

    for (int k0 = 0; k0 < K; k0 += 32) {
        // ---- stage A tile 128x32 (1024 float4s; 4 per thread), cvt to tf32 ----
#pragma unroll
        for (int i = 0; i < 4; i++) {
            int f = tid + i * 256;
            int r = f >> 3, c = (f & 7) * 4;
            int grow = row0 + r;
            float4 v = make_float4(0.f, 0.f, 0.f, 0.f);
            if (grow < M)
                v = *reinterpret_cast<const float4*>(A + (size_t)grow * K + k0 + c);
            uint4 u;
            u.x = f2tf32(v.x); u.y = f2tf32(v.y); u.z = f2tf32(v.z); u.w = f2tf32(v.w);
            *reinterpret_cast<uint4*>(&As[r][c]) = u;
        }
        // ---- stage B tile 32x128 ----
#pragma unroll
        for (int i = 0; i < 4; i++) {
            int f = tid + i * 256;
            int r = f >> 5, c = (f & 31) * 4;
            float4 v = *reinterpret_cast<const float4*>(B + (size_t)(k0 + r) * N + col0 + c);
            uint4 u;
            u.x = f2tf32(v.x); u.y = f2tf32(v.y); u.z = f2tf32(v.z); u.w = f2tf32(v.w);
            *reinterpret_cast<uint4*>(&Bs[r][c]) = u;
        }
        __syncthreads();

        // ---- 4 k-steps of m16n8k8 ----
#pragma unroll
        for (int ks = 0; ks < 4; ks++) {
            uint32_t a[4][4], b[4][2];
            const int kk = ks * 8;
#pragma unroll
            for (int mf = 0; mf < 4; mf++) {
                int m = warpM * 64 + mf * 16;
                a[mf][0] = As[m + g][kk + tg];
                a[mf][1] = As[m + g + 8][kk + tg];
                a[mf][2] = As[m + g][kk + tg + 4];
                a[mf][3] = As[m + g + 8][kk + tg + 4];
            }
#pragma unroll
            for (int nf = 0; nf < 4; nf++) {
                int n = warpN * 32 + nf * 8 + g;
                b[nf][0] = Bs[kk + tg][n];
                b[nf][1] = Bs[kk + tg + 4][n];
            }
#pragma unroll
            for (int mf = 0; mf < 4; mf++)
#pragma unroll
                for (int nf = 0; nf < 4; nf++)
                    mma_tf32(acc[mf][nf], a[mf], b[nf]);
        }
        __syncthreads();
    }

    // ---- epilogue: bias (+GELU), float2 stores ----
#pragma unroll
    for (int mf = 0; mf < 4; mf++) {
#pragma unroll
        for (int half = 0; half < 2; half++) {
            int row = row0 + warpM * 64 + mf * 16 + g + half * 8;
            if (row >= M) continue;
#pragma unroll
            for (int nf = 0; nf < 4; nf++) {
                int col = col0 + warpN * 32 + nf * 8 + 2 * tg;
                float v0 = acc[mf][nf][half * 2 + 0] + bias[col];
                float v1 = acc[mf][nf][half * 2 + 1] + bias[col + 1];
                if (EPI == 1) {
                    float c3 = v0 * v0 * v0;
                    v0 = 0.5f * v0 * (1.f + tanhf(0.7978845608028654f * (v0 + 0.044715f * c3)));
                    c3 = v1 * v1 * v1;
                    v1 = 0.5f * v1 * (1.f + tanhf(0.7978845608028654f * (v1 + 0.044715f * c3)));
                }
                *reinterpret_cast<float2*>(C + (size_t)row * N + col) = make_float2(v0, v1);
            }
        }
    }
}

// ---------------- LayerNorm: warp per node, 256 dims (8 per lane) ----------------
__global__ void layernorm_k(const float* __restrict__ x, const float* __restrict__ g,
                            const float* __restrict__ b, float* __restrict__ out, int n)
{
    int w = (blockIdx.x * blockDim.x + threadIdx.x) >> 5;
    int lane = threadIdx.x & 31;
    if (w >= n) return;
    const float* xp = x + (size_t)w * DIM;
    float v[8], s = 0.f, sq = 0.f;
#pragma unroll
    for (int j = 0; j < 8; j++) {
        v[j] = xp[lane + j * 32];
        s += v[j];
        sq += v[j] * v[j];
    }
#pragma unroll
    for (int o = 16; o; o >>= 1) {
        s += __shfl_xor_sync(0xffffffffu, s, o);
        sq += __shfl_xor_sync(0xffffffffu, sq, o);
    }
    float mean = s * (1.f / DIM);
    float var = sq * (1.f / DIM) - mean * mean;
    float rstd = rsqrtf(var + LNEPS);
#pragma unroll
    for (int j = 0; j < 8; j++) {
        int d = lane + j * 32;
        out[(size_t)w * DIM + d] = (v[j] - mean) * rstd * g[d] + b[d];
    }
}

// ---------------- gated residual ----------------
__global__ void gated_residual_k(const float* __restrict__ y, const float* __restrict__ res,
                                 const float* __restrict__ gw, float* __restrict__ xout, int n)
{
    int w = (blockIdx.x * blockDim.x + threadIdx.x) >> 5;
    int lane = threadIdx.x & 31;
    if (w >= n) return;
    const float* yp = y + (size_t)w * DIM;
    const float* rp = res + (size_t)w * DIM;
    float s = 0.f;
#pragma unroll
    for (int j = 0; j < 8; j++) {
        int d = lane + j * 32;
        float yv = yp[d], rv = rp[d];
        s += yv * gw[d] + rv * gw[DIM + d] + (yv - rv) * gw[2 * DIM + d];
    }
#pragma unroll
    for (int o = 16; o; o >>= 1) s += __shfl_xor_sync(0xffffffffu, s, o);
    float gate = 1.f / (1.f + expf(-s));
#pragma unroll
    for (int j = 0; j < 8; j++) {
        int d = lane + j * 32;
        float yv = yp[d], rv = rp[d];
        xout[(size_t)w * DIM + d] = yv * gate + rv * (1.f - gate);
    }
}

// ---------------- attention ----------------
__device__ __forceinline__ void atomicMaxFloat(float* addr, float val)
{
    int old = __float_as_int(*addr);
    while (__int_as_float(old) < val) {
        int prev = atomicCAS(reinterpret_cast<int*>(addr), old, __float_as_int(val));
        if (prev == old) break;
        old = prev;
    }
}

__global__ void fill_k(float* p, float v, int n)
{
    int i = blockIdx.x * blockDim.x + threadIdx.x;
    if (i < n) p[i] = v;
}

__global__ void sim_max_k(const float* __restrict__ q, const float* __restrict__ kv,
                          const float* __restrict__ eb, const int* __restrict__ src,
                          const int* __restrict__ dst, float* __restrict__ sim,
                          float* __restrict__ mbuf, int ne)
{
    int w = (blockIdx.x * blockDim.x + threadIdx.x) >> 5;
    int lane = threadIdx.x & 31;
    if (w >= ne) return;
    int s = src[w], d = dst[w];
    const float* qp = q + (size_t)d * INNER;
    const float* kp = kv + (size_t)s * (2 * INNER);
    const float* ep = eb + (size_t)w * INNER;
#pragma unroll
    for (int h = 0; h < HEADS; h++) {
        int base = h * DH + lane * 2;
        float2 qv = *reinterpret_cast<const float2*>(qp + base);
        float2 kvv = *reinterpret_cast<const float2*>(kp + base);
        float2 ev = *reinterpret_cast<const float2*>(ep + base);
        float p = qv.x * (kvv.x + ev.x) + qv.y * (kvv.y + ev.y);
#pragma unroll
        for (int o = 16; o; o >>= 1) p += __shfl_xor_sync(0xffffffffu, p, o);
        if (lane == 0) {
            float sv = p * 0.125f;
            sim[w * HEADS + h] = sv;
            atomicMaxFloat(&mbuf[d * HEADS + h], sv);
        }
    }
}

__global__ void exp_den_k(float* __restrict__ sim, const float* __restrict__ mbuf,
                          const int* __restrict__ dst, float* __restrict__ den, int total)
{
    int i = blockIdx.x * blockDim.x + threadIdx.x;
    if (i >= total) return;
    int e = i >> 2, h = i & 3;
    int d = dst[e];
    float p = expf(sim[i] - mbuf[d * HEADS + h]);
    sim[i] = p;
    atomicAdd(&den[d * HEADS + h], p);
}

__global__ void attn_agg_k(const float* __restrict__ kv, const float* __restrict__ eb,
                           const float* __restrict__ p, const float* __restrict__ den,
                           const int* __restrict__ src, const int* __restrict__ dst,
                           float* __restrict__ agg, int ne)
{
    int w = (blockIdx.x * blockDim.x + threadIdx.x) >> 5;
    int lane = threadIdx.x & 31;
    if (w >= ne) return;
    int s = src[w], d = dst[w];
    float attn[HEADS];
#pragma unroll
    for (int h = 0; h < HEADS; h++)
        attn[h] = p[w * HEADS + h] / den[d * HEADS + h];
    const float* vp = kv + (size_t)s * (2 * INNER) + INNER;
    const float* ep = eb + (size_t)w * INNER;
    float* ap = agg + (size_t)d * INNER;
#pragma unroll
    for (int j = 0; j < 8; j++) {
        int dim = lane + j * 32;
        int h = dim >> 6;
        atomicAdd(&ap[dim], attn[h] * (vp[dim] + ep[dim]));
    }
}

// ---------------- host side ----------------
static inline dim3 gemm_grid(int M, int N) { return dim3((N + 127) / 128, (M + 127) / 128); }

extern "C" void kernel_launch(void* const* d_in, const int* in_sizes, int n_in,
                              void* d_out, int out_size)
{
    const float* x_in      = (const float*)d_in[0];
    const float* edge_attr = (const float*)d_in[1];
    const int*   edge_idx  = (const int*)d_in[2];
    const float* ln1_g = (const float*)d_in[3];
    const float* ln1_b = (const float*)d_in[4];
    const float* Wq  = (const float*)d_in[5];
    const float* bq  = (const float*)d_in[6];
    const float* Wkv = (const float*)d_in[7];
    const float* bkv = (const float*)d_in[8];
    const float* We  = (const float*)d_in[9];
    const float* be  = (const float*)d_in[10];
    const float* Wo  = (const float*)d_in[11];
    const float* bo  = (const float*)d_in[12];
    const float* gate_attn_W = (const float*)d_in[13];
    const float* ln2_g = (const float*)d_in[14];
    const float* ln2_b = (const float*)d_in[15];
    const float* Wff1 = (const float*)d_in[16];
    const float* bff1 = (const float*)d_in[17];
    const float* Wff2 = (const float*)d_in[18];
    const float* bff2 = (const float*)d_in[19];
    const float* gate_ff_W = (const float*)d_in[20];
    const float* Wproj = (const float*)d_in[21];
    const float* bproj = (const float*)d_in[22];
    float* out = (float*)d_out;

    const int* src = edge_idx;       // row 0
    const int* dst = edge_idx + EE;  // row 1

    float *px, *pxn, *pq, *pkv, *pe, *psim, *pm, *pden, *pagg, *py, *pff;
    cudaGetSymbolAddress((void**)&px, g_x);
    cudaGetSymbolAddress((void**)&pxn, g_xn);
    cudaGetSymbolAddress((void**)&pq, g_q);
    cudaGetSymbolAddress((void**)&pkv, g_kv);
    cudaGetSymbolAddress((void**)&pe, g_e);
    cudaGetSymbolAddress((void**)&psim, g_sim);
    cudaGetSymbolAddress((void**)&pm, g_m);
    cudaGetSymbolAddress((void**)&pden, g_den);
    cudaGetSymbolAddress((void**)&pagg, g_agg);
    cudaGetSymbolAddress((void**)&py, g_y);
    cudaGetSymbolAddress((void**)&pff, g_ff);

    cudaMemcpyAsync(px, x_in, (size_t)NN * DIM * sizeof(float), cudaMemcpyDeviceToDevice, 0);

    const int warpBlocks_N = (NN * 32 + 255) / 256;
    const int warpBlocks_E = (EE * 32 + 255) / 256;

    for (int d = 0; d < DEPTH; d++) {
        const float* l1g = ln1_g + d * DIM;
        const float* l1b = ln1_b + d * DIM;
        const float* wq  = Wq  + (size_t)d * DIM * INNER;
        const float* bqd = bq  + d * INNER;
        const float* wkv = Wkv + (size_t)d * DIM * 2 * INNER;
        const float* bkvd = bkv + d * 2 * INNER;
        const float* we  = We  + (size_t)d * EDIM * INNER;
        const float* bed = be  + d * INNER;
        const float* wo  = Wo  + (size_t)d * INNER * DIM;
        const float* bod = bo  + d * DIM;
        const float* gaw = gate_attn_W + (size_t)d * 3 * DIM;
        const float* l2g = ln2_g + d * DIM;
        const float* l2b = ln2_b + d * DIM;
        const float* wf1 = Wff1 + (size_t)d * DIM * FF;
        const float* bf1 = bff1 + d * FF;
        const float* wf2 = Wff2 + (size_t)d * FF * DIM;
        const float* bf2 = bff2 + d * DIM;
        const float* gfw = gate_ff_W + (size_t)d * 3 * DIM;

        layernorm_k<<<warpBlocks_N, 256>>>(px, l1g, l1b, pxn, NN);
        tgemm_bias<0><<<gemm_grid(NN, INNER), 256>>>(pxn, wq, bqd, pq, NN, INNER, DIM);
        tgemm_bias<0><<<gemm_grid(NN, 2 * INNER), 256>>>(pxn, wkv, bkvd, pkv, NN, 2 * INNER, DIM);
        tgemm_bias<0><<<gemm_grid(EE, INNER), 256>>>(edge_attr, we, bed, pe, EE, INNER, EDIM);

        fill_k<<<(NN * HEADS + 255) / 256, 256>>>(pm, -3.0e38f, NN * HEADS);
        cudaMemsetAsync(pden, 0, (size_t)NN * HEADS * sizeof(float), 0);
        cudaMemsetAsync(pagg, 0, (size_t)NN * INNER * sizeof(float), 0);

        sim_max_k<<<warpBlocks_E, 256>>>(pq, pkv, pe, src, dst, psim, pm, EE);
        exp_den_k<<<(EE * HEADS + 255) / 256, 256>>>(psim, pm, dst, pden, EE * HEADS);
        attn_agg_k<<<warpBlocks_E, 256>>>(pkv, pe, psim, pden, src, dst, pagg, EE);

        tgemm_bias<0><<<gemm_grid(NN, DIM), 256>>>(pagg, wo, bod, py, NN, DIM, INNER);
        gated_residual_k<<<warpBlocks_N, 256>>>(py, px, gaw, px, NN);

        layernorm_k<<<warpBlocks_N, 256>>>(px, l2g, l2b, pxn, NN);
        tgemm_bias<1><<<gemm_grid(NN, FF), 256>>>(pxn, wf1, bf1, pff, NN, FF, DIM);
        tgemm_bias<0><<<gemm_grid(NN, DIM), 256>>>(pff, wf2, bf2, py, NN, DIM, FF);
        gated_residual_k<<<warpBlocks_N, 256>>>(py, px, gfw, px, NN);
    }

    tgemm_bias<0><<<gemm_grid(NN, OUTD), 256>>>(px, Wproj, bproj, out, NN, OUTD, DIM);
}

// round 3
// speedup vs baseline: 2.9654x; 1.1477x over previous
#include <cuda_runtime.h>
#include <cuda_bf16.h>
#include <cstdint>

// ---------------- problem constants ----------------
#define NN 20000
#define EE 200000
#define DIM 256
#define HEADS 4
#define DH 64
#define INNER 256
#define EDIM 512
#define FF 1024
#define OUTD 128
#define DEPTH 2
#define LNEPS 1e-5f

// ---------------- scratch (device globals; no allocation allowed) ----------------
__device__ float g_x[NN * DIM];
__device__ float g_xn[NN * DIM];
__device__ float g_q[NN * INNER];
__device__ float g_kv[NN * 2 * INNER];
__device__ float g_e[(size_t)EE * INNER];
__device__ float g_sim[EE * HEADS];
__device__ float g_m[NN * HEADS];
__device__ float g_den[NN * HEADS];
__device__ float g_agg[NN * INNER];
__device__ float g_y[NN * DIM];
__device__ float g_ff[NN * FF];
// pre-rounded tf32 weights
#define WQ_OFF   0
#define WKV_OFF  131072
#define WE_OFF   393216
#define WO_OFF   655360
#define WF1_OFF  786432
#define WF2_OFF  1310720
#define WPROJ_OFF 1835008
#define WT_TOTAL 1867776
__device__ float g_wt[WT_TOTAL];

// ---------------- helpers ----------------
__device__ __forceinline__ uint32_t f2tf32(float f)
{
    uint32_t r;
    asm("cvt.rna.tf32.f32 %0, %1;" : "=r"(r) : "f"(f));
    return r;
}

__device__ __forceinline__ void mma_tf32(float* c, const uint32_t* a, const uint32_t* b)
{
    asm volatile(
        "mma.sync.aligned.m16n8k8.row.col.f32.tf32.tf32.f32 "
        "{%0,%1,%2,%3}, {%4,%5,%6,%7}, {%8,%9}, {%0,%1,%2,%3};"
        : "+f"(c[0]), "+f"(c[1]), "+f"(c[2]), "+f"(c[3])
        : "r"(a[0]), "r"(a[1]), "r"(a[2]), "r"(a[3]), "r"(b[0]), "r"(b[1]));
}

__device__ __forceinline__ uint32_t smem_u32(const void* p)
{
    return (uint32_t)__cvta_generic_to_shared(p);
}

// ---------------- TF32 tensor-core GEMM v3 ----------------
// BM=BN=128, BK=32, 128 threads (4 warps, 2x2), warp tile 64x64.
// cp.async double-buffered staging (inputs must already be tf32-encoded, or
// accept HW truncation), ldmatrix A fragments, conflict-free B (stride 136).
// smem: As[2][128][36] u32 + Bs[2][32][136] u32 = 71680 B dynamic.
#define AS_STRIDE 36
#define BS_STRIDE 136
#define SMEM_WORDS (2 * 128 * AS_STRIDE + 2 * 32 * BS_STRIDE)

template <int EPI>  // 0 = bias only, 1 = bias + tanh-GELU (+ tf32 rounding of output)
__global__ __launch_bounds__(128, 2) void tgemm_v3(
    const float* __restrict__ A, const float* __restrict__ B,
    const float* __restrict__ bias, float* __restrict__ C,
    int M, int N, int K)
{
    extern __shared__ uint32_t smem[];
    uint32_t* As = smem;                          // [2][128][36]
    uint32_t* Bs = smem + 2 * 128 * AS_STRIDE;    // [2][32][136]

    const int tid = threadIdx.x;
    const int warp = tid >> 5, lane = tid & 31;
    const int warpM = warp >> 1, warpN = warp & 1;
    const int g = lane >> 2, tg = lane & 3;
    const int row0 = blockIdx.y * 128, col0 = blockIdx.x * 128;

    // ldmatrix lane -> (row, col) within a 16x8 A fragment tile
    const int lm_row = (lane & 7) + ((lane >> 3) & 1) * 8;
    const int lm_col = (lane >> 4) * 4;

    float acc[4][8][4];
#pragma unroll
    for (int i = 0; i < 4; i++)
#pragma unroll
        for (int j = 0; j < 8; j++)
#pragma unroll
            for (int r = 0; r < 4; r++) acc[i][j][r] = 0.f;

    auto stage = [&](int buf, int k0) {
        // A tile 128x32 floats: 1024 16B-chunks, 8 per thread
#pragma unroll
        for (int i = 0; i < 8; i++) {
            int c = tid + 128 * i;
            int r = c >> 3, cc = (c & 7) * 4;
            int grow = row0 + r;
            int sz = (grow < M) ? 16 : 0;
            if (grow >= M) grow = M - 1;  // keep address in-range
            const float* src = A + (size_t)grow * K + k0 + cc;
            uint32_t dst = smem_u32(&As[(buf * 128 + r) * AS_STRIDE + cc]);
            asm volatile("cp.async.cg.shared.global [%0], [%1], 16, %2;"
                         :: "r"(dst), "l"(src), "r"(sz));
        }
        // B tile 32x128 floats
#pragma unroll
        for (int i = 0; i < 8; i++) {
            int c = tid + 128 * i;
            int r = c >> 5, cc = (c & 31) * 4;
            const float* src = B + (size_t)(k0 + r) * N + col0 + cc;
            uint32_t dst = smem_u32(&Bs[(buf * 32 + r) * BS_STRIDE + cc]);
            asm volatile("cp.async.cg.shared.global [%0], [%1], 16, 16;"
                         :: "r"(dst), "l"(src));
        }
        asm volatile("cp.async.commit_group;");
    };

    const int nk = K >> 5;
    stage(0, 0);

    for (int t = 0; t < nk; t++) {
        if (t + 1 < nk) {
            stage((t + 1) & 1, (t + 1) * 32);
            asm volatile("cp.async.wait_group 1;");
        } else {
            asm volatile("cp.async.wait_group 0;");
        }
        __syncthreads();

        const uint32_t* Ab = As + (size_t)(t & 1) * 128 * AS_STRIDE;
        const uint32_t* Bb = Bs + (size_t)(t & 1) * 32 * BS_STRIDE;

#pragma unroll
        for (int ks = 0; ks < 4; ks++) {
            const int kk = ks * 8;
            uint32_t a[4][4], b[8][2];
#pragma unroll
            for (int mf = 0; mf < 4; mf++) {
                int m0 = warpM * 64 + mf * 16;
                uint32_t addr = smem_u32(&Ab[(m0 + lm_row) * AS_STRIDE + kk + lm_col]);
                asm volatile("ldmatrix.sync.aligned.m8n8.x4.shared.b16 {%0,%1,%2,%3}, [%4];"
                             : "=r"(a[mf][0]), "=r"(a[mf][1]), "=r"(a[mf][2]), "=r"(a[mf][3])
                             : "r"(addr));
            }
#pragma unroll
            for (int nf = 0; nf < 8; nf++) {
                int n = warpN * 64 + nf * 8 + g;
                b[nf][0] = Bb[(kk + tg) * BS_STRIDE + n];
                b[nf][1] = Bb[(kk + tg + 4) * BS_STRIDE + n];
            }
#pragma unroll
            for (int mf = 0; mf < 4; mf++)
#pragma unroll
                for (int nf = 0; nf < 8; nf++)
                    mma_tf32(acc[mf][nf], a[mf], b[nf]);
        }
        __syncthreads();
    }

    // ---- epilogue ----
#pragma unroll
    for (int mf = 0; mf < 4; mf++) {
#pragma unroll
        for (int half = 0; half < 2; half++) {
            int row = row0 + warpM * 64 + mf * 16 + g + half * 8;
            if (row >= M) continue;
#pragma unroll
            for (int nf = 0; nf < 8; nf++) {
                int col = col0 + warpN * 64 + nf * 8 + 2 * tg;
                float v0 = acc[mf][nf][half * 2 + 0] + bias[col];
                float v1 = acc[mf][nf][half * 2 + 1] + bias[col + 1];
                if (EPI == 1) {
                    float c3 = v0 * v0 * v0;
                    v0 = 0.5f * v0 * (1.f + tanhf(0.7978845608028654f * (v0 + 0.044715f * c3)));
                    c3 = v1 * v1 * v1;
                    v1 = 0.5f * v1 * (1.f + tanhf(0.7978845608028654f * (v1 + 0.044715f * c3)));
                    v0 = __uint_as_float(f2tf32(v0));  // pre-round for next GEMM
                    v1 = __uint_as_float(f2tf32(v1));
                }
                *reinterpret_cast<float2*>(C + (size_t)row * N + col) = make_float2(v0, v1);
            }
        }
    }
}

// ---------------- weight tf32 pre-conversion ----------------
__global__ void cvt_tf32_k(const float* __restrict__ in, float* __restrict__ out, int n)
{
    int i = blockIdx.x * blockDim.x + threadIdx.x;
    if (i < n) out[i] = __uint_as_float(f2tf32(in[i]));
}

// ---------------- LayerNorm (output rounded to tf32 for GEMM consumers) ----------------
__global__ void layernorm_k(const float* __restrict__ x, const float* __restrict__ g,
                            const float* __restrict__ b, float* __restrict__ out, int n)
{
    int w = (blockIdx.x * blockDim.x + threadIdx.x) >> 5;
    int lane = threadIdx.x & 31;
    if (w >= n) return;
    const float* xp = x + (size_t)w * DIM;
    float v[8], s = 0.f, sq = 0.f;
#pragma unroll
    for (int j = 0; j < 8; j++) {
        v[j] = xp[lane + j * 32];
        s += v[j];
        sq += v[j] * v[j];
    }
#pragma unroll
    for (int o = 16; o; o >>= 1) {
        s += __shfl_xor_sync(0xffffffffu, s, o);
        sq += __shfl_xor_sync(0xffffffffu, sq, o);
    }
    float mean = s * (1.f / DIM);
    float var = sq * (1.f / DIM) - mean * mean;
    float rstd = rsqrtf(var + LNEPS);
#pragma unroll
    for (int j = 0; j < 8; j++) {
        int d = lane + j * 32;
        float o2 = (v[j] - mean) * rstd * g[d] + b[d];
        out[(size_t)w * DIM + d] = __uint_as_float(f2tf32(o2));
    }
}

// ---------------- gated residual ----------------
__global__ void gated_residual_k(const float* __restrict__ y, const float* __restrict__ res,
                                 const float* __restrict__ gw, float* __restrict__ xout, int n)
{
    int w = (blockIdx.x * blockDim.x + threadIdx.x) >> 5;
    int lane = threadIdx.x & 31;
    if (w >= n) return;
    const float* yp = y + (size_t)w * DIM;
    const float* rp = res + (size_t)w * DIM;
    float s = 0.f;
#pragma unroll
    for (int j = 0; j < 8; j++) {
        int d = lane + j * 32;
        float yv = yp[d], rv = rp[d];
        s += yv * gw[d] + rv * gw[DIM + d] + (yv - rv) * gw[2 * DIM + d];
    }
#pragma unroll
    for (int o = 16; o; o >>= 1) s += __shfl_xor_sync(0xffffffffu, s, o);
    float gate = 1.f / (1.f + expf(-s));
#pragma unroll
    for (int j = 0; j < 8; j++) {
        int d = lane + j * 32;
        float yv = yp[d], rv = rp[d];
        xout[(size_t)w * DIM + d] = yv * gate + rv * (1.f - gate);
    }
}

// ---------------- attention ----------------
__device__ __forceinline__ void atomicMaxFloat(float* addr, float val)
{
    int old = __float_as_int(*addr);
    while (__int_as_float(old) < val) {
        int prev = atomicCAS(reinterpret_cast<int*>(addr), old, __float_as_int(val));
        if (prev == old) break;
        old = prev;
    }
}

__global__ void fill_k(float* p, float v, int n)
{
    int i = blockIdx.x * blockDim.x + threadIdx.x;
    if (i < n) p[i] = v;
}

__global__ void sim_max_k(const float* __restrict__ q, const float* __restrict__ kv,
                          const float* __restrict__ eb, const int* __restrict__ src,
                          const int* __restrict__ dst, float* __restrict__ sim,
                          float* __restrict__ mbuf, int ne)
{
    int w = (blockIdx.x * blockDim.x + threadIdx.x) >> 5;
    int lane = threadIdx.x & 31;
    if (w >= ne) return;
    int s = src[w], d = dst[w];
    const float* qp = q + (size_t)d * INNER;
    const float* kp = kv + (size_t)s * (2 * INNER);
    const float* ep = eb + (size_t)w * INNER;
#pragma unroll
    for (int h = 0; h < HEADS; h++) {
        int base = h * DH + lane * 2;
        float2 qv = *reinterpret_cast<const float2*>(qp + base);
        float2 kvv = *reinterpret_cast<const float2*>(kp + base);
        float2 ev = *reinterpret_cast<const float2*>(ep + base);
        float p = qv.x * (kvv.x + ev.x) + qv.y * (kvv.y + ev.y);
#pragma unroll
        for (int o = 16; o; o >>= 1) p += __shfl_xor_sync(0xffffffffu, p, o);
        if (lane == 0) {
            float sv = p * 0.125f;
            sim[w * HEADS + h] = sv;
            atomicMaxFloat(&mbuf[d * HEADS + h], sv);
        }
    }
}

__global__ void exp_den_k(float* __restrict__ sim, const float* __restrict__ mbuf,
                          const int* __restrict__ dst, float* __restrict__ den, int total)
{
    int i = blockIdx.x * blockDim.x + threadIdx.x;
    if (i >= total) return;
    int e = i >> 2, h = i & 3;
    int d = dst[e];
    float p = expf(sim[i] - mbuf[d * HEADS + h]);
    sim[i] = p;
    atomicAdd(&den[d * HEADS + h], p);
}

__global__ void attn_agg_k(const float* __restrict__ kv, const float* __restrict__ eb,
                           const float* __restrict__ p, const float* __restrict__ den,
                           const int* __restrict__ src, const int* __restrict__ dst,
                           float* __restrict__ agg, int ne)
{
    int w = (blockIdx.x * blockDim.x + threadIdx.x) >> 5;
    int lane = threadIdx.x & 31;
    if (w >= ne) return;
    int s = src[w], d = dst[w];
    float attn[HEADS];
#pragma unroll
    for (int h = 0; h < HEADS; h++)
        attn[h] = p[w * HEADS + h] / den[d * HEADS + h];
    const float* vp = kv + (size_t)s * (2 * INNER) + INNER;
    const float* ep = eb + (size_t)w * INNER;
    float* ap = agg + (size_t)d * INNER;
#pragma unroll
    for (int j = 0; j < 8; j++) {
        int dim = lane + j * 32;
        int h = dim >> 6;
        atomicAdd(&ap[dim], attn[h] * (vp[dim] + ep[dim]));
    }
}

// ---------------- host side ----------------
static inline dim3 gemm_grid(int M, int N) { return dim3((N + 127) / 128, (M + 127) / 128); }
#define SMEM_BYTES (SMEM_WORDS * 4)

extern "C" void kernel_launch(void* const* d_in, const int* in_sizes, int n_in,
                              void* d_out, int out_size)
{
    const float* x_in      = (const float*)d_in[0];
    const float* edge_attr = (const float*)d_in[1];
    const int*   edge_idx  = (const int*)d_in[2];
    const float* ln1_g = (const float*)d_in[3];
    const float* ln1_b = (const float*)d_in[4];
    const float* Wq  = (const float*)d_in[5];
    const float* bq  = (const float*)d_in[6];
    const float* Wkv = (const float*)d_in[7];
    const float* bkv = (const float*)d_in[8];
    const float* We  = (const float*)d_in[9];
    const float* be  = (const float*)d_in[10];
    const float* Wo  = (const float*)d_in[11];
    const float* bo  = (const float*)d_in[12];
    const float* gate_attn_W = (const float*)d_in[13];
    const float* ln2_g = (const float*)d_in[14];
    const float* ln2_b = (const float*)d_in[15];
    const float* Wff1 = (const float*)d_in[16];
    const float* bff1 = (const float*)d_in[17];
    const float* Wff2 = (const float*)d_in[18];
    const float* bff2 = (const float*)d_in[19];
    const float* gate_ff_W = (const float*)d_in[20];
    const float* Wproj = (const float*)d_in[21];
    const float* bproj = (const float*)d_in[22];
    float* out = (float*)d_out;

    const int* src = edge_idx;
    const int* dst = edge_idx + EE;

    float *px, *pxn, *pq, *pkv, *pe, *psim, *pm, *pden, *pagg, *py, *pff, *pwt;
    cudaGetSymbolAddress((void**)&px, g_x);
    cudaGetSymbolAddress((void**)&pxn, g_xn);
    cudaGetSymbolAddress((void**)&pq, g_q);
    cudaGetSymbolAddress((void**)&pkv, g_kv);
    cudaGetSymbolAddress((void**)&pe, g_e);
    cudaGetSymbolAddress((void**)&psim, g_sim);
    cudaGetSymbolAddress((void**)&pm, g_m);
    cudaGetSymbolAddress((void**)&pden, g_den);
    cudaGetSymbolAddress((void**)&pagg, g_agg);
    cudaGetSymbolAddress((void**)&py, g_y);
    cudaGetSymbolAddress((void**)&pff, g_ff);
    cudaGetSymbolAddress((void**)&pwt, g_wt);

    static bool attr_set = false;
    if (!attr_set) {
        cudaFuncSetAttribute(tgemm_v3<0>, cudaFuncAttributeMaxDynamicSharedMemorySize, SMEM_BYTES);
        cudaFuncSetAttribute(tgemm_v3<1>, cudaFuncAttributeMaxDynamicSharedMemorySize, SMEM_BYTES);
        attr_set = true;
    }

    cudaMemcpyAsync(px, x_in, (size_t)NN * DIM * sizeof(float), cudaMemcpyDeviceToDevice, 0);

    // pre-round all weights to tf32 (runs every replay; deterministic)
    cvt_tf32_k<<<(2 * DIM * INNER + 255) / 256, 256>>>(Wq, pwt + WQ_OFF, 2 * DIM * INNER);
    cvt_tf32_k<<<(2 * DIM * 2 * INNER + 255) / 256, 256>>>(Wkv, pwt + WKV_OFF, 2 * DIM * 2 * INNER);
    cvt_tf32_k<<<(2 * EDIM * INNER + 255) / 256, 256>>>(We, pwt + WE_OFF, 2 * EDIM * INNER);
    cvt_tf32_k<<<(2 * INNER * DIM + 255) / 256, 256>>>(Wo, pwt + WO_OFF, 2 * INNER * DIM);
    cvt_tf32_k<<<(2 * DIM * FF + 255) / 256, 256>>>(Wff1, pwt + WF1_OFF, 2 * DIM * FF);
    cvt_tf32_k<<<(2 * FF * DIM + 255) / 256, 256>>>(Wff2, pwt + WF2_OFF, 2 * FF * DIM);
    cvt_tf32_k<<<(DIM * OUTD + 255) / 256, 256>>>(Wproj, pwt + WPROJ_OFF, DIM * OUTD);

    const int warpBlocks_N = (NN * 32 + 255) / 256;
    const int warpBlocks_E = (EE * 32 + 255) / 256;

    for (int d = 0; d < DEPTH; d++) {
        const float* l1g = ln1_g + d * DIM;
        const float* l1b = ln1_b + d * DIM;
        const float* wq  = pwt + WQ_OFF  + (size_t)d * DIM * INNER;
        const float* bqd = bq  + d * INNER;
        const float* wkv = pwt + WKV_OFF + (size_t)d * DIM * 2 * INNER;
        const float* bkvd = bkv + d * 2 * INNER;
        const float* we  = pwt + WE_OFF  + (size_t)d * EDIM * INNER;
        const float* bed = be  + d * INNER;
        const float* wo  = pwt + WO_OFF  + (size_t)d * INNER * DIM;
        const float* bod = bo  + d * DIM;
        const float* gaw = gate_attn_W + (size_t)d * 3 * DIM;
        const float* l2g = ln2_g + d * DIM;
        const float* l2b = ln2_b + d * DIM;
        const float* wf1 = pwt + WF1_OFF + (size_t)d * DIM * FF;
        const float* bf1 = bff1 + d * FF;
        const float* wf2 = pwt + WF2_OFF + (size_t)d * FF * DIM;
        const float* bf2 = bff2 + d * DIM;
        const float* gfw = gate_ff_W + (size_t)d * 3 * DIM;

        layernorm_k<<<warpBlocks_N, 256>>>(px, l1g, l1b, pxn, NN);
        tgemm_v3<0><<<gemm_grid(NN, INNER), 128, SMEM_BYTES>>>(pxn, wq, bqd, pq, NN, INNER, DIM);
        tgemm_v3<0><<<gemm_grid(NN, 2 * INNER), 128, SMEM_BYTES>>>(pxn, wkv, bkvd, pkv, NN, 2 * INNER, DIM);
        tgemm_v3<0><<<gemm_grid(EE, INNER), 128, SMEM_BYTES>>>(edge_attr, we, bed, pe, EE, INNER, EDIM);

        fill_k<<<(NN * HEADS + 255) / 256, 256>>>(pm, -3.0e38f, NN * HEADS);
        cudaMemsetAsync(pden, 0, (size_t)NN * HEADS * sizeof(float), 0);
        cudaMemsetAsync(pagg, 0, (size_t)NN * INNER * sizeof(float), 0);

        sim_max_k<<<warpBlocks_E, 256>>>(pq, pkv, pe, src, dst, psim, pm, EE);
        exp_den_k<<<(EE * HEADS + 255) / 256, 256>>>(psim, pm, dst, pden, EE * HEADS);
        attn_agg_k<<<warpBlocks_E, 256>>>(pkv, pe, psim, pden, src, dst, pagg, EE);

        tgemm_v3<0><<<gemm_grid(NN, DIM), 128, SMEM_BYTES>>>(pagg, wo, bod, py, NN, DIM, INNER);
        gated_residual_k<<<warpBlocks_N, 256>>>(py, px, gaw, px, NN);

        layernorm_k<<<warpBlocks_N, 256>>>(px, l2g, l2b, pxn, NN);
        tgemm_v3<1><<<gemm_grid(NN, FF), 128, SMEM_BYTES>>>(pxn, wf1, bf1, pff, NN, FF, DIM);
        tgemm_v3<0><<<gemm_grid(NN, DIM), 128, SMEM_BYTES>>>(pff, wf2, bf2, py, NN, DIM, FF);
        gated_residual_k<<<warpBlocks_N, 256>>>(py, px, gfw, px, NN);
    }

    tgemm_v3<0><<<gemm_grid(NN, OUTD), 128, SMEM_BYTES>>>(px, pwt + WPROJ_OFF, bproj, out, NN, OUTD, DIM);
}